// round 1
// baseline (speedup 1.0000x reference)
#include <cuda_runtime.h>

#define HH 112
#define WW 112
#define CIN 64
#define COUTC 128
#define NBATCH 32

// Scratch: quantized int8 activations packed as int32 words (4 channels/word),
// and quantized+transposed weights packed for int4 loads.
__device__ int g_Xq[NBATCH * HH * WW * (CIN / 4)];   // 6,422,528 ints = ~25.7 MB
__device__ int g_Wq[9 * 16 * COUTC];                 // 18,432 ints = 72 KB

// ---------------------------------------------------------------------------
// Quantize activations: q = clip(round_to_nearest_even(x*128), -128, 127)
// packed 4 int8 channels per int32 word, NHWC order preserved.
// ---------------------------------------------------------------------------
__global__ void quant_x_kernel(const float* __restrict__ x, int nwords) {
    int i = blockIdx.x * blockDim.x + threadIdx.x;
    if (i >= nwords) return;
    float4 v = ((const float4*)x)[i];
    int a = min(127, max(-128, __float2int_rn(v.x * 128.f)));
    int b = min(127, max(-128, __float2int_rn(v.y * 128.f)));
    int c = min(127, max(-128, __float2int_rn(v.z * 128.f)));
    int d = min(127, max(-128, __float2int_rn(v.w * 128.f)));
    g_Xq[i] = (a & 0xFF) | ((b & 0xFF) << 8) | ((c & 0xFF) << 16) | (d << 24);
}

// ---------------------------------------------------------------------------
// Quantize + transpose weights.
// Input  HWIO: k[((khw)*64 + c)*128 + cout], khw = ky*3+kx
// Output layout: for chunk j = khw*4 + (cw>>2)  (cw = c/4 in [0,16)):
//   int32 word (channels 4cw..4cw+3 of cout) at g_Wq[j*512 + cout*4 + (cw&3)]
// so the conv kernel can do one int4 load per (khw, cq, cout):
//   ((const int4*)g_Wq)[(khw*4+cq)*128 + cout]  -> 16 channels.
// ---------------------------------------------------------------------------
__global__ void quant_w_kernel(const float* __restrict__ k) {
    int o = blockIdx.x * blockDim.x + threadIdx.x;
    if (o >= 9 * 16 * COUTC) return;
    int khw  = o >> 11;        // / 2048
    int rem  = o & 2047;
    int cw   = rem >> 7;       // 0..15
    int cout = rem & 127;
    int word = 0;
#pragma unroll
    for (int b = 0; b < 4; b++) {
        float v = k[(khw * 64 + cw * 4 + b) * COUTC + cout];
        int q = min(127, max(-128, __float2int_rn(v * 128.f)));
        word |= (q & 0xFF) << (8 * b);
    }
    g_Wq[(khw * 4 + (cw >> 2)) * 512 + cout * 4 + (cw & 3)] = word;
}

// ---------------------------------------------------------------------------
// Conv: block = 16 output pixels (one row segment) x 128 couts, 256 threads.
//   thread t: cout = t&127, pixel half = t>>7 (8 pixels each).
// Shared input tile: rows y-1..y+1, cols x0-1..x0+16, all 64 channels
//   as int32 words: sx[3][18][16] = 3456 B. Compute-loop smem reads are
//   warp-uniform (address independent of cout) -> full broadcast, N=1.
// Exact integer accumulation via dp4a; output = floor(S/128)/128 (all exact).
// ---------------------------------------------------------------------------
__global__ __launch_bounds__(256) void conv_dp4a_kernel(float* __restrict__ out) {
    __shared__ int sx[3][18][16];
    int tid = threadIdx.x;
    int x0  = blockIdx.x * 16;
    int y   = blockIdx.y;
    int n   = blockIdx.z;

    // Cooperative tile load with zero padding
    for (int i = tid; i < 3 * 18 * 16; i += 256) {
        int r   = i / 288;
        int rem = i - r * 288;
        int col = rem >> 4;
        int cw  = rem & 15;
        int h = y - 1 + r;
        int w = x0 - 1 + col;
        int v = 0;
        if (h >= 0 && h < HH && w >= 0 && w < WW)
            v = g_Xq[((n * HH + h) * WW + w) * 16 + cw];
        sx[r][col][cw] = v;
    }
    __syncthreads();

    int cout = tid & 127;
    int px   = (tid >> 7) * 8;

    int acc[8];
#pragma unroll
    for (int p = 0; p < 8; p++) acc[p] = 0;

    const int4* Wq4 = (const int4*)g_Wq;

#pragma unroll
    for (int ky = 0; ky < 3; ky++) {
#pragma unroll
        for (int kx = 0; kx < 3; kx++) {
            int khw = ky * 3 + kx;
#pragma unroll
            for (int cq = 0; cq < 4; cq++) {
                int4 wv = Wq4[(khw * 4 + cq) * COUTC + cout];
#pragma unroll
                for (int p = 0; p < 8; p++) {
                    int4 xv = *(const int4*)&sx[ky][px + p + kx][cq * 4];
                    acc[p] = __dp4a(xv.x, wv.x, acc[p]);
                    acc[p] = __dp4a(xv.y, wv.y, acc[p]);
                    acc[p] = __dp4a(xv.z, wv.z, acc[p]);
                    acc[p] = __dp4a(xv.w, wv.w, acc[p]);
                }
            }
        }
    }

    // out = floor((S / 16384) * 128) / 128 = floor(S * 2^-7) * 2^-7  (exact in fp32)
    long long base = ((long long)(n * HH + y) * WW + x0) * COUTC + cout;
#pragma unroll
    for (int p = 0; p < 8; p++) {
        float r = floorf((float)acc[p] * 0.0078125f) * 0.0078125f;
        out[base + (long long)(px + p) * COUTC] = r;
    }
}

extern "C" void kernel_launch(void* const* d_in, const int* in_sizes, int n_in,
                              void* d_out, int out_size) {
    const float* x = (const float*)d_in[0];   // [32,112,112,64] fp32 NHWC
    const float* k = (const float*)d_in[1];   // [3,3,64,128] fp32 HWIO
    float* out = (float*)d_out;               // [32,112,112,128] fp32

    int nwords = NBATCH * HH * WW * (CIN / 4);
    quant_x_kernel<<<(nwords + 255) / 256, 256>>>(x, nwords);
    quant_w_kernel<<<(9 * 16 * COUTC + 255) / 256, 256>>>(k);

    dim3 grid(WW / 16, HH, NBATCH);
    conv_dp4a_kernel<<<grid, 256>>>(out);
}

// round 6
// speedup vs baseline: 1.5732x; 1.5732x over previous
#include <cuda_runtime.h>
#include <cstdint>

#define HH 112
#define WW 112
#define CIN 64
#define COUTC 128
#define NB 32
#define NTILES 3136          // 32 images * (112/8 row-groups) * (112/16 col-groups)
#define GRID_CONV 304

// Scratch: quantized int8 activations (4 per int32 word, NHWC), and quantized
// weights re-laid-out as [tap][cout][cin] int8 with the SMEM chunk swizzle
// pre-applied (so the conv kernel copies bytes linearly).
__device__ __align__(16) int g_Xq[NB * HH * WW * (CIN / 4)];   // ~25.7 MB
__device__ __align__(16) unsigned char g_W[9 * COUTC * CIN];   // 72 KB

// ---------------------------------------------------------------------------
// helpers
// ---------------------------------------------------------------------------
__device__ __forceinline__ uint32_t smem_u32(const void* p) {
    uint32_t a;
    asm("{ .reg .u64 t; cvta.to.shared.u64 t, %1; cvt.u32.u64 %0, t; }" : "=r"(a) : "l"(p));
    return a;
}
#define CP_ASYNC16(dst, src) \
    asm volatile("cp.async.cg.shared.global [%0], [%1], 16;\n" :: "r"(dst), "l"(src))
#define CP_COMMIT()   asm volatile("cp.async.commit_group;\n" ::: "memory")
#define CP_WAIT(N)    asm volatile("cp.async.wait_group %0;\n" :: "n"(N) : "memory")
#define STS_ZERO16(dst) \
    asm volatile("st.shared.v4.b32 [%0], {%1,%1,%1,%1};" :: "r"(dst), "r"(0) : "memory")

#define LDSM_X4(r, addr)                                                          \
    asm volatile("ldmatrix.sync.aligned.m8n8.x4.shared.b16 {%0,%1,%2,%3}, [%4];"  \
        : "=r"((r)[0]), "=r"((r)[1]), "=r"((r)[2]), "=r"((r)[3]) : "r"(addr))

#define MMA_S8(c, A, B0, B1)                                                      \
    asm volatile("mma.sync.aligned.m16n8k32.row.col.s32.s8.s8.s32 "               \
        "{%0,%1,%2,%3},{%4,%5,%6,%7},{%8,%9},{%0,%1,%2,%3};"                      \
        : "+r"((c)[0]), "+r"((c)[1]), "+r"((c)[2]), "+r"((c)[3])                  \
        : "r"((A)[0]), "r"((A)[1]), "r"((A)[2]), "r"((A)[3]), "r"(B0), "r"(B1))

// ---------------------------------------------------------------------------
// Prep: quantize activations -> packed int8 (round-half-even, clip) NHWC
// ---------------------------------------------------------------------------
__global__ void quant_x_kernel(const float* __restrict__ x, int nwords) {
    int i = blockIdx.x * blockDim.x + threadIdx.x;
    if (i >= nwords) return;
    float4 v = ((const float4*)x)[i];
    int a = min(127, max(-128, __float2int_rn(v.x * 128.f)));
    int b = min(127, max(-128, __float2int_rn(v.y * 128.f)));
    int c = min(127, max(-128, __float2int_rn(v.z * 128.f)));
    int d = min(127, max(-128, __float2int_rn(v.w * 128.f)));
    g_Xq[i] = (a & 0xFF) | ((b & 0xFF) << 8) | ((c & 0xFF) << 16) | (d << 24);
}

// ---------------------------------------------------------------------------
// Prep: quantize weights HWIO -> [tap][cout][cin] int8 with chunk swizzle:
// 64B row per cout; 16B chunk c stored at c ^ ((cout>>1)&3).
// ---------------------------------------------------------------------------
__global__ void quant_w_kernel(const float* __restrict__ k) {
    int o = blockIdx.x * blockDim.x + threadIdx.x;     // (tap*64+cin)*128+cout
    if (o >= 9 * CIN * COUTC) return;
    int tap  = o >> 13;
    int rem  = o & 8191;
    int cin  = rem >> 7;
    int cout = rem & 127;
    int q = min(127, max(-128, __float2int_rn(k[o] * 128.f)));
    int chunk = (cin >> 4) ^ ((cout >> 1) & 3);
    g_W[tap * 8192 + cout * 64 + chunk * 16 + (cin & 15)] = (unsigned char)q;
}

// ---------------------------------------------------------------------------
// Conv: persistent CTAs, 256 threads, int8 mma.sync (m16n8k32).
// SMEM: A double buffer 2x8KB @0, W 72KB @16384.  Total 90112 B.
// Warp grid 4(M32) x 2(N64). 18 k-steps (9 taps x 2 k-halves of 32).
// ---------------------------------------------------------------------------
#define SMEM_W     16384
#define SMEM_BYTES 90112

__global__ __launch_bounds__(256, 2) void conv_imma_kernel(float* __restrict__ out) {
    extern __shared__ __align__(128) char smem[];
    const int tid  = threadIdx.x;
    const int wid  = tid >> 5;
    const int lane = tid & 31;
    const uint32_t sb = smem_u32(smem);
    const uint32_t sA[2] = { sb, sb + 8192 };
    const uint32_t sW = sb + SMEM_W;

    // Prologue: load all 9 weight tap tiles (72 KB), pre-swizzled
    for (int j = tid; j < 4608; j += 256)
        CP_ASYNC16(sW + j * 16, (const char*)g_W + j * 16);
    CP_COMMIT();
    CP_WAIT(0);
    __syncthreads();

    const int m0 = (wid & 3) * 32;   // warp M offset (pixels)
    const int n0 = (wid >> 2) * 64;  // warp N offset (couts)

    // ldmatrix lane-invariant address pieces
    const int rA   = m0 + ((lane >> 3) & 1) * 8 + (lane & 7);   // A tile row (m-tile 0)
    const int csA  = lane >> 4;                                  // A chunk select
    const int swA  = (rA >> 1) & 3;
    const uint32_t offA = (uint32_t)rA * 64;
    const int rB   = n0 + (lane >> 4) * 8 + (lane & 7);          // W row (pair 0)
    const int csB  = (lane >> 3) & 1;
    const int swB  = (rB >> 1) & 3;
    const uint32_t offB = (uint32_t)rB * 64;

    // fill lane mapping: thread t fills row t>>1, chunks (t&1)*2 .. +1
    const int frow = tid >> 1;
    const int fc0  = (tid & 1) * 2;
    const int frr  = frow >> 4;
    const int fcc  = frow & 15;
    const int fsw  = (frow >> 1) & 3;

    for (int T = blockIdx.x; T < NTILES; T += gridDim.x) {
        const int n  = T / 98;
        const int rm = T - n * 98;
        const int r0 = (rm / 7) * 8;
        const int c0 = (rm % 7) * 16;

        int acc[2][8][4];
#pragma unroll
        for (int mt = 0; mt < 2; mt++)
#pragma unroll
            for (int nt = 0; nt < 8; nt++)
#pragma unroll
                for (int j = 0; j < 4; j++) acc[mt][nt][j] = 0;

        // fill(tap) into buffer tap&1
#define FILL_TAP(tap_) do {                                                        \
        const int ky = (tap_) / 3, kx = (tap_) - ky * 3;                           \
        const int h = r0 + frr + ky - 1;                                           \
        const int w = c0 + fcc + kx - 1;                                           \
        const uint32_t ab = sA[(tap_) & 1] + (uint32_t)frow * 64;                  \
        if (((unsigned)h < HH) && ((unsigned)w < WW)) {                            \
            const char* src = (const char*)(g_Xq + ((size_t)(n * HH + h) * WW + w) * 16); \
            CP_ASYNC16(ab + (uint32_t)((fc0    ) ^ fsw) * 16, src + fc0 * 16);     \
            CP_ASYNC16(ab + (uint32_t)((fc0 + 1) ^ fsw) * 16, src + fc0 * 16 + 16);\
        } else {                                                                   \
            STS_ZERO16(ab + (uint32_t)((fc0    ) ^ fsw) * 16);                     \
            STS_ZERO16(ab + (uint32_t)((fc0 + 1) ^ fsw) * 16);                     \
        }                                                                          \
    } while (0)

        FILL_TAP(0);
        CP_COMMIT();

#pragma unroll 1
        for (int tap = 0; tap < 9; tap++) {
            if (tap < 8) { FILL_TAP(tap + 1); CP_COMMIT(); CP_WAIT(1); }
            else         { CP_WAIT(0); }
            __syncthreads();

            const uint32_t ab = sA[tap & 1];
            const uint32_t wb = sW + (uint32_t)tap * 8192;
#pragma unroll
            for (int kh = 0; kh < 2; kh++) {
                const int kc = kh * 2;
                uint32_t a0[4], a1[4];
                LDSM_X4(a0, ab + offA        + (uint32_t)((kc + csA) ^ swA) * 16);
                LDSM_X4(a1, ab + offA + 1024 + (uint32_t)((kc + csA) ^ swA) * 16);
#pragma unroll
                for (int p = 0; p < 4; p++) {
                    uint32_t b[4];
                    LDSM_X4(b, wb + offB + (uint32_t)p * 1024 +
                               (uint32_t)((kc + csB) ^ swB) * 16);
                    MMA_S8(acc[0][2 * p],     a0, b[0], b[1]);
                    MMA_S8(acc[0][2 * p + 1], a0, b[2], b[3]);
                    MMA_S8(acc[1][2 * p],     a1, b[0], b[1]);
                    MMA_S8(acc[1][2 * p + 1], a1, b[2], b[3]);
                }
            }
            __syncthreads();
        }

        // Epilogue: out = floor(acc * 2^-7) * 2^-7   (exact)
#pragma unroll
        for (int mt = 0; mt < 2; mt++) {
            const int px1 = m0 + mt * 16 + (lane >> 2);
            const int px2 = px1 + 8;
            float* o1 = out + (((size_t)(n * HH + r0 + (px1 >> 4)) * WW +
                                (c0 + (px1 & 15))) << 7);
            float* o2 = out + (((size_t)(n * HH + r0 + (px2 >> 4)) * WW +
                                (c0 + (px2 & 15))) << 7);
            const int col = n0 + (lane & 3) * 2;
#pragma unroll
            for (int nt = 0; nt < 8; nt++) {
                float2 v;
                v.x = floorf((float)acc[mt][nt][0] * 0.0078125f) * 0.0078125f;
                v.y = floorf((float)acc[mt][nt][1] * 0.0078125f) * 0.0078125f;
                *(float2*)(o1 + col + nt * 8) = v;
                v.x = floorf((float)acc[mt][nt][2] * 0.0078125f) * 0.0078125f;
                v.y = floorf((float)acc[mt][nt][3] * 0.0078125f) * 0.0078125f;
                *(float2*)(o2 + col + nt * 8) = v;
            }
        }
    }
}

extern "C" void kernel_launch(void* const* d_in, const int* in_sizes, int n_in,
                              void* d_out, int out_size) {
    const float* x = (const float*)d_in[0];   // [32,112,112,64] fp32 NHWC
    const float* k = (const float*)d_in[1];   // [3,3,64,128] fp32 HWIO
    float* out = (float*)d_out;               // [32,112,112,128] fp32

    cudaFuncSetAttribute(conv_imma_kernel,
                         cudaFuncAttributeMaxDynamicSharedMemorySize, SMEM_BYTES);

    int nwords = NB * HH * WW * CIN / 4;
    quant_x_kernel<<<(nwords + 255) / 256, 256>>>(x, nwords);
    quant_w_kernel<<<(9 * CIN * COUTC + 255) / 256, 256>>>(k);
    conv_imma_kernel<<<GRID_CONV, 256, SMEM_BYTES>>>(out);
}